// round 9
// baseline (speedup 1.0000x reference)
#include <cuda_runtime.h>
#include <cuda_bf16.h>
#include <math.h>
#include <stdint.h>

#define NLEV 16
#define TMASK ((1u << 19) - 1u)
#define PR1 2654435761u
#define PR2 805459861u
#define PR3 3674653429u
#define NMAX 2097152
#define NCHUNK 8
#define CHUNK 262144

// plane-major feature scratch: word c of point i at g_feat[c*NMAX + i]
// c in [0,32): bf16x2 hi words; c+32: lo words. 64 * 2M * 4B = 512 MB.
__device__ uint32_t g_feat[64ull * NMAX];
// time-fused dynamic tables: 16 levels x 512K float2 = 64 MB
__device__ float2 g_tbl_dyn[(size_t)NLEV << 19];

struct ResParams { int r[NLEV]; };

// ---------------- helpers ----------------
__device__ __forceinline__ void mma16816(float d[4], const uint32_t a[4], uint32_t b0, uint32_t b1) {
    asm volatile("mma.sync.aligned.m16n8k16.row.col.f32.bf16.bf16.f32 "
        "{%0,%1,%2,%3}, {%4,%5,%6,%7}, {%8,%9}, {%0,%1,%2,%3};"
        : "+f"(d[0]), "+f"(d[1]), "+f"(d[2]), "+f"(d[3])
        : "r"(a[0]), "r"(a[1]), "r"(a[2]), "r"(a[3]), "r"(b0), "r"(b1));
}

__device__ __forceinline__ void split2(float v0, float v1, uint32_t& hi, uint32_t& lo) {
    __nv_bfloat162 h, l;
    h.x = __float2bfloat16_rn(v0);
    h.y = __float2bfloat16_rn(v1);
    l.x = __float2bfloat16_rn(v0 - __bfloat162float(h.x));
    l.y = __float2bfloat16_rn(v1 - __bfloat162float(h.y));
    hi = *reinterpret_cast<uint32_t*>(&h);
    lo = *reinterpret_cast<uint32_t*>(&l);
}

__device__ __forceinline__ float bf2sum(uint32_t hi, uint32_t lo, int idx) {
    const __nv_bfloat162* h = reinterpret_cast<const __nv_bfloat162*>(&hi);
    const __nv_bfloat162* l = reinterpret_cast<const __nv_bfloat162*>(&lo);
    return idx == 0 ? (__bfloat162float(h->x) + __bfloat162float(l->x))
                    : (__bfloat162float(h->y) + __bfloat162float(l->y));
}

// elementwise float2 lerp: a + f*(b-a)
__device__ __forceinline__ float2 lerp2(float2 a, float2 b, float f) {
    float2 r;
    r.x = fmaf(f, b.x - a.x, a.x);
    r.y = fmaf(f, b.y - a.y, a.y);
    return r;
}

// ---------------- 3D hash-grid level encode (factored lerp tree) ----------------
__device__ __forceinline__ void enc3(const float2* __restrict__ tb, float x0, float x1, float x2,
                                     int R, float& o0, float& o1) {
    float fr = (float)R;
    float p0 = x0 * fr, p1 = x1 * fr, p2 = x2 * fr;
    float g0 = floorf(p0), g1 = floorf(p1), g2 = floorf(p2);
    float f0 = p0 - g0, f1 = p1 - g1, f2 = p2 - g2;
    unsigned i0 = (unsigned)(int)g0, i1 = (unsigned)(int)g1, i2 = (unsigned)(int)g2;
    unsigned hy0 = i1 * PR1, hy1 = hy0 + PR1;
    unsigned hz0 = i2 * PR2, hz1 = hz0 + PR2;
    unsigned hyz[4] = { hy0 ^ hz0, hy0 ^ hz1, hy1 ^ hz0, hy1 ^ hz1 };
    unsigned i0b = i0 + 1u;
    float2 v[8];
#pragma unroll
    for (int j = 0; j < 4; j++) {
        v[j]     = __ldg(tb + ((i0  ^ hyz[j]) & TMASK));
        v[4 + j] = __ldg(tb + ((i0b ^ hyz[j]) & TMASK));
    }
    float2 u0 = lerp2(v[0], v[4], f0);
    float2 u1 = lerp2(v[1], v[5], f0);
    float2 u2 = lerp2(v[2], v[6], f0);
    float2 u3 = lerp2(v[3], v[7], f0);
    float2 s0 = lerp2(u0, u2, f1);
    float2 s1 = lerp2(u1, u3, f1);
    float2 r  = lerp2(s0, s1, f2);
    o0 = r.x; o1 = r.y;
}

// ================= kernel P: fold scalar t into the dynamic tables =================
__global__ void __launch_bounds__(256)
fuse_dyn_kernel(const float* __restrict__ tptr,
                const float* __restrict__ tbl_d, ResParams rp) {
    const int l = blockIdx.y;
    const unsigned j = blockIdx.x * 256 + threadIdx.x;
    const float tv = __ldg(tptr);
    const float p3 = tv * (float)rp.r[l];
    const float g3 = floorf(p3);
    const float f3 = p3 - g3;
    const unsigned i3 = (unsigned)(int)g3;
    const unsigned hw0 = (i3 * PR3) & TMASK;
    const unsigned hw1 = ((i3 + 1u) * PR3) & TMASK;
    const float2* tb = (const float2*)tbl_d + ((size_t)l << 19);
    float2 a = __ldg(tb + (j ^ hw0));
    float2 b = __ldg(tb + (j ^ hw1));
    g_tbl_dyn[((size_t)l << 19) + j] = lerp2(a, b, f3);
}

// ================= kernel A: level-parallel hash-grid encode (chunked) =================
__global__ void __launch_bounds__(256)
encode_kernel(const float* __restrict__ x,
              const float* __restrict__ tbl_s,
              int offset, int N, ResParams rp) {
    const int i = offset + blockIdx.x * 256 + threadIdx.x;
    if (i >= N) return;
    const int lv = blockIdx.y;

    const float2* tb = (lv < 16)
        ? (const float2*)tbl_s + ((size_t)lv << 19)
        : (const float2*)g_tbl_dyn + ((size_t)(lv - 16) << 19);

    const float x0 = x[3 * i], x1 = x[3 * i + 1], x2 = x[3 * i + 2];
    float a0, a1;
    enc3(tb, x0, x1, x2, rp.r[lv & 15], a0, a1);

    uint32_t hi, lo;
    split2(a0, a1, hi, lo);
    __stcs(&g_feat[(size_t)lv * NMAX + i], hi);
    __stcs(&g_feat[(size_t)(32 + lv) * NMAX + i], lo);
}

// ================= kernel B: 5-layer MLP via HMMA (chunked) =================
#define BTPB 256
#define BWARP 8
#define W22_OFF 81920
#define BSMEM (81920 + 256)

__global__ void __launch_bounds__(BTPB, 2)
mlp_kernel(const float* __restrict__ w10, const float* __restrict__ w11,
           const float* __restrict__ w12, const float* __restrict__ w20,
           const float* __restrict__ w21, const float* __restrict__ w22,
           const float* __restrict__ alphap,
           float* __restrict__ out, int offset, int N) {
    extern __shared__ char sm[];
    const int tid = threadIdx.x;
    const int wid = tid >> 5;
    const int lane = tid & 31;
    const int gq = lane >> 2;   // quad row 0..7
    const int cq = lane & 3;    // quad col 0..3

    // ---- stage weight fragments (B-fragment order, bf16 hi/lo) ----
    {
        const float* Ws[5] = { w10, w11, w12, w20, w21 };
#pragma unroll 1
        for (int g = wid; g < 320; g += BWARP) {
            int layer = g >> 6;
            int rem = g & 63;
            int tile = rem >> 1;          // kt*8 + nt
            int j = rem & 1;
            int kt = tile >> 3;
            int k0 = kt * 16 + cq * 2 + j * 8;
            int n = (tile & 7) * 8 + gq;
            const float* W = Ws[layer];
            float v0 = __ldg(W + k0 * 64 + n);
            float v1 = __ldg(W + (k0 + 1) * 64 + n);
            uint32_t hi, lo;
            split2(v0, v1, hi, lo);
            char* base = sm + layer * 16384 + tile * 256 + lane * 8 + j * 4;
            *reinterpret_cast<uint32_t*>(base) = hi;
            *reinterpret_cast<uint32_t*>(base + 8192) = lo;
        }
        if (tid < 64) ((float*)(sm + W22_OFF))[tid] = w22[tid];
    }
    __syncthreads();

    const float alpha = __ldg(alphap);
    const float beta = 1.f - alpha;

#pragma unroll 1
    for (int mt = 0; mt < 2; mt++) {
        const int base_row = offset + blockIdx.x * BTPB + wid * 32 + mt * 16;
        uint32_t ahi[16], alo[16];

#pragma unroll
        for (int layer = 0; layer < 5; layer++) {
            float d[8][4];
#pragma unroll
            for (int nt = 0; nt < 8; nt++)
#pragma unroll
                for (int q = 0; q < 4; q++) d[nt][q] = 0.f;

            const char* wl = sm + layer * 16384;

#pragma unroll
            for (int kt = 0; kt < 4; kt++) {
                uint32_t Ah[4], Al[4];
                if (layer == 0) {
                    size_t p0 = (size_t)(kt * 8 + cq) * NMAX + base_row + gq;
                    Ah[0] = __ldcs(&g_feat[p0]);
                    Ah[1] = __ldcs(&g_feat[p0 + 8]);
                    Ah[2] = __ldcs(&g_feat[p0 + 4ull * NMAX]);
                    Ah[3] = __ldcs(&g_feat[p0 + 4ull * NMAX + 8]);
                    Al[0] = __ldcs(&g_feat[p0 + 32ull * NMAX]);
                    Al[1] = __ldcs(&g_feat[p0 + 32ull * NMAX + 8]);
                    Al[2] = __ldcs(&g_feat[p0 + 36ull * NMAX]);
                    Al[3] = __ldcs(&g_feat[p0 + 36ull * NMAX + 8]);
                } else {
#pragma unroll
                    for (int q = 0; q < 4; q++) { Ah[q] = ahi[kt * 4 + q]; Al[q] = alo[kt * 4 + q]; }
                }
#pragma unroll
                for (int nt = 0; nt < 8; nt++) {
                    const char* tb = wl + (kt * 8 + nt) * 256 + lane * 8;
                    uint2 bh = *reinterpret_cast<const uint2*>(tb);
                    uint2 bl = *reinterpret_cast<const uint2*>(tb + 8192);
                    mma16816(d[nt], Ah, bh.x, bh.y);
                    mma16816(d[nt], Ah, bl.x, bl.y);
                    mma16816(d[nt], Al, bh.x, bh.y);
                }
            }

            if (layer < 4) {
#pragma unroll
                for (int nt = 0; nt < 8; nt++) {
#pragma unroll
                    for (int q = 0; q < 4; q++) d[nt][q] = fmaxf(d[nt][q], 0.f);
                    if (layer == 2) {
                        size_t pw = (size_t)(nt * 4 + cq) * NMAX + base_row + gq;
                        uint32_t h0 = __ldcs(&g_feat[pw]);
                        uint32_t l0 = __ldcs(&g_feat[pw + 32ull * NMAX]);
                        uint32_t h8 = __ldcs(&g_feat[pw + 8]);
                        uint32_t l8 = __ldcs(&g_feat[pw + 32ull * NMAX + 8]);
                        d[nt][0] = d[nt][0] * alpha + beta * bf2sum(h0, l0, 0);
                        d[nt][1] = d[nt][1] * alpha + beta * bf2sum(h0, l0, 1);
                        d[nt][2] = d[nt][2] * alpha + beta * bf2sum(h8, l8, 0);
                        d[nt][3] = d[nt][3] * alpha + beta * bf2sum(h8, l8, 1);
                    }
                }
#pragma unroll
                for (int kt = 0; kt < 4; kt++) {
                    split2(d[2 * kt][0],     d[2 * kt][1],     ahi[kt * 4 + 0], alo[kt * 4 + 0]);
                    split2(d[2 * kt][2],     d[2 * kt][3],     ahi[kt * 4 + 1], alo[kt * 4 + 1]);
                    split2(d[2 * kt + 1][0], d[2 * kt + 1][1], ahi[kt * 4 + 2], alo[kt * 4 + 2]);
                    split2(d[2 * kt + 1][2], d[2 * kt + 1][3], ahi[kt * 4 + 3], alo[kt * 4 + 3]);
                }
            } else {
                float s0 = 0.f, s1 = 0.f;
#pragma unroll
                for (int nt = 0; nt < 8; nt++) {
                    float2 wv = *reinterpret_cast<const float2*>(sm + W22_OFF + nt * 32 + cq * 8);
                    s0 = fmaf(fmaxf(d[nt][0], 0.f), wv.x, s0);
                    s0 = fmaf(fmaxf(d[nt][1], 0.f), wv.y, s0);
                    s1 = fmaf(fmaxf(d[nt][2], 0.f), wv.x, s1);
                    s1 = fmaf(fmaxf(d[nt][3], 0.f), wv.y, s1);
                }
                s0 += __shfl_xor_sync(0xFFFFFFFF, s0, 1);
                s0 += __shfl_xor_sync(0xFFFFFFFF, s0, 2);
                s1 += __shfl_xor_sync(0xFFFFFFFF, s1, 1);
                s1 += __shfl_xor_sync(0xFFFFFFFF, s1, 2);
                if (cq == 0) {
                    int r0 = base_row + gq;
                    if (r0 < N) out[r0] = s0;
                    if (r0 + 8 < N) out[r0 + 8] = s1;
                }
            }
        }
    }
}

// host-side lazily-created side stream + events (host objects; no device allocations)
static cudaStream_t g_side = nullptr;
static cudaEvent_t g_ev[NCHUNK];
static cudaEvent_t g_join = nullptr;

extern "C" void kernel_launch(void* const* d_in, const int* in_sizes, int n_in,
                              void* d_out, int out_size) {
    (void)in_sizes; (void)n_in;
    const float* x      = (const float*)d_in[0];
    const float* t      = (const float*)d_in[1];
    const float* tbl_s  = (const float*)d_in[2];
    const float* tbl_d  = (const float*)d_in[3];
    const float* w10    = (const float*)d_in[4];
    const float* w11    = (const float*)d_in[5];
    const float* w12    = (const float*)d_in[6];
    const float* w20    = (const float*)d_in[7];
    const float* w21    = (const float*)d_in[8];
    const float* w22    = (const float*)d_in[9];
    const float* alpha  = (const float*)d_in[10];
    float* out = (float*)d_out;

    int N = out_size;
    if (N <= 0) return;
    if (N > NMAX) N = NMAX;

    if (g_side == nullptr) {
        cudaStreamCreateWithFlags(&g_side, cudaStreamNonBlocking);
        for (int c = 0; c < NCHUNK; c++)
            cudaEventCreateWithFlags(&g_ev[c], cudaEventDisableTiming);
        cudaEventCreateWithFlags(&g_join, cudaEventDisableTiming);
        cudaFuncSetAttribute(mlp_kernel, cudaFuncAttributeMaxDynamicSharedMemorySize, BSMEM);
    }

    // RES[l] = floor(16 * b^l), identical double-precision expr as reference
    ResParams rp;
    double b = pow(2048.0 / 16.0, 1.0 / 15.0);
    for (int l = 0; l < NLEV; l++)
        rp.r[l] = (int)floor(16.0 * pow(b, (double)l));

    // fold scalar t into dynamic tables (4D -> 3D) on the main (capture) stream
    dim3 gridP(2048, 16);
    fuse_dyn_kernel<<<gridP, 256>>>(t, tbl_d, rp);

    // chunked encode on main stream; MLP chunks forked onto side stream
    int nchunks = (N + CHUNK - 1) / CHUNK;
    if (nchunks > NCHUNK) nchunks = NCHUNK;  // N <= NMAX = NCHUNK*CHUNK

    for (int c = 0; c < nchunks; c++) {
        int off = c * CHUNK;
        int cn = (N - off < CHUNK) ? (N - off) : CHUNK;
        dim3 gridA((cn + 255) / 256, 32);
        encode_kernel<<<gridA, 256>>>(x, tbl_s, off, N, rp);
        cudaEventRecord(g_ev[c], 0);
    }
    for (int c = 0; c < nchunks; c++) {
        int off = c * CHUNK;
        int cn = (N - off < CHUNK) ? (N - off) : CHUNK;
        cudaStreamWaitEvent(g_side, g_ev[c], 0);
        int blocksB = (cn + BTPB - 1) / BTPB;
        mlp_kernel<<<blocksB, BTPB, BSMEM, g_side>>>(w10, w11, w12, w20, w21, w22, alpha, out, off, N);
    }
    cudaEventRecord(g_join, g_side);
    cudaStreamWaitEvent(0, g_join, 0);
}

// round 10
// speedup vs baseline: 1.1712x; 1.1712x over previous
#include <cuda_runtime.h>
#include <cuda_bf16.h>
#include <math.h>
#include <stdint.h>

#define NLEV 16
#define TMASK ((1u << 19) - 1u)
#define PR1 2654435761u
#define PR2 805459861u
#define PR3 3674653429u
#define NMAX 2097152

// plane-major feature scratch: word c of point i at g_feat[c*NMAX + i]
// c in [0,32): bf16x2 hi words; c+32: lo words. 64 * 2M * 4B = 512 MB.
__device__ uint32_t g_feat[64ull * NMAX];
// time-fused dynamic tables: 16 levels x 512K float2 = 64 MB
__device__ float2 g_tbl_dyn[(size_t)NLEV << 19];

struct ResParams { int r[NLEV]; };

// ---------------- helpers ----------------
__device__ __forceinline__ void mma16816(float d[4], const uint32_t a[4], uint32_t b0, uint32_t b1) {
    asm volatile("mma.sync.aligned.m16n8k16.row.col.f32.bf16.bf16.f32 "
        "{%0,%1,%2,%3}, {%4,%5,%6,%7}, {%8,%9}, {%0,%1,%2,%3};"
        : "+f"(d[0]), "+f"(d[1]), "+f"(d[2]), "+f"(d[3])
        : "r"(a[0]), "r"(a[1]), "r"(a[2]), "r"(a[3]), "r"(b0), "r"(b1));
}

__device__ __forceinline__ void split2(float v0, float v1, uint32_t& hi, uint32_t& lo) {
    __nv_bfloat162 h, l;
    h.x = __float2bfloat16_rn(v0);
    h.y = __float2bfloat16_rn(v1);
    l.x = __float2bfloat16_rn(v0 - __bfloat162float(h.x));
    l.y = __float2bfloat16_rn(v1 - __bfloat162float(h.y));
    hi = *reinterpret_cast<uint32_t*>(&h);
    lo = *reinterpret_cast<uint32_t*>(&l);
}

__device__ __forceinline__ float bf2sum(uint32_t hi, uint32_t lo, int idx) {
    const __nv_bfloat162* h = reinterpret_cast<const __nv_bfloat162*>(&hi);
    const __nv_bfloat162* l = reinterpret_cast<const __nv_bfloat162*>(&lo);
    return idx == 0 ? (__bfloat162float(h->x) + __bfloat162float(l->x))
                    : (__bfloat162float(h->y) + __bfloat162float(l->y));
}

// elementwise float2 lerp: a + f*(b-a)
__device__ __forceinline__ float2 lerp2(float2 a, float2 b, float f) {
    float2 r;
    r.x = fmaf(f, b.x - a.x, a.x);
    r.y = fmaf(f, b.y - a.y, a.y);
    return r;
}

// ---------------- 3D hash-grid level encode (paired-corner loads + lerp tree) ----------------
__device__ __forceinline__ void enc3(const float2* __restrict__ tb, float x0, float x1, float x2,
                                     int R, float& o0, float& o1) {
    float fr = (float)R;
    float p0 = x0 * fr, p1 = x1 * fr, p2 = x2 * fr;
    float g0 = floorf(p0), g1 = floorf(p1), g2 = floorf(p2);
    float f0 = p0 - g0, f1 = p1 - g1, f2 = p2 - g2;
    unsigned i0 = (unsigned)(int)g0, i1 = (unsigned)(int)g1, i2 = (unsigned)(int)g2;
    unsigned hy0 = i1 * PR1, hy1 = hy0 + PR1;
    unsigned hz0 = i2 * PR2, hz1 = hz0 + PR2;
    unsigned hyz[4] = { hy0 ^ hz0, hy0 ^ hz1, hy1 ^ hz0, hy1 ^ hz1 };
    float2 vlo[4], vhi[4];   // x=0 / x=1 corners per (y,z) combo
    if ((i0 & 1u) == 0u) {
        // even i0: x-corner pair = adjacent table entries -> one float4 load
#pragma unroll
        for (int j = 0; j < 4; j++) {
            unsigned j0 = (i0 ^ hyz[j]) & TMASK;
            float4 p = __ldg(reinterpret_cast<const float4*>(tb) + (j0 >> 1));
            if (j0 & 1u) { vlo[j] = make_float2(p.z, p.w); vhi[j] = make_float2(p.x, p.y); }
            else         { vlo[j] = make_float2(p.x, p.y); vhi[j] = make_float2(p.z, p.w); }
        }
    } else {
        unsigned i0b = i0 + 1u;
#pragma unroll
        for (int j = 0; j < 4; j++) {
            vlo[j] = __ldg(tb + ((i0  ^ hyz[j]) & TMASK));
            vhi[j] = __ldg(tb + ((i0b ^ hyz[j]) & TMASK));
        }
    }
    float2 u0 = lerp2(vlo[0], vhi[0], f0);
    float2 u1 = lerp2(vlo[1], vhi[1], f0);
    float2 u2 = lerp2(vlo[2], vhi[2], f0);
    float2 u3 = lerp2(vlo[3], vhi[3], f0);
    float2 s0 = lerp2(u0, u2, f1);
    float2 s1 = lerp2(u1, u3, f1);
    float2 r  = lerp2(s0, s1, f2);
    o0 = r.x; o1 = r.y;
}

// ================= kernel P: fold scalar t into the dynamic tables =================
__global__ void __launch_bounds__(256)
fuse_dyn_kernel(const float* __restrict__ tptr,
                const float* __restrict__ tbl_d, ResParams rp) {
    const int l = blockIdx.y;
    const unsigned j = blockIdx.x * 256 + threadIdx.x;
    const float tv = __ldg(tptr);
    const float p3 = tv * (float)rp.r[l];
    const float g3 = floorf(p3);
    const float f3 = p3 - g3;
    const unsigned i3 = (unsigned)(int)g3;
    const unsigned hw0 = (i3 * PR3) & TMASK;
    const unsigned hw1 = ((i3 + 1u) * PR3) & TMASK;
    const float2* tb = (const float2*)tbl_d + ((size_t)l << 19);
    float2 a = __ldg(tb + (j ^ hw0));
    float2 b = __ldg(tb + (j ^ hw1));
    g_tbl_dyn[((size_t)l << 19) + j] = lerp2(a, b, f3);
}

// ================= kernel A: level-parallel hash-grid encode =================
// grid = (ceil(N/256), 32): blockIdx.y = level slot (0-15 static, 16-31 time-fused dynamic)
__global__ void __launch_bounds__(256)
encode_kernel(const float* __restrict__ x,
              const float* __restrict__ tbl_s,
              int N, ResParams rp) {
    const int i = blockIdx.x * 256 + threadIdx.x;
    if (i >= N) return;
    const int lv = blockIdx.y;

    const float2* tb = (lv < 16)
        ? (const float2*)tbl_s + ((size_t)lv << 19)
        : (const float2*)g_tbl_dyn + ((size_t)(lv - 16) << 19);

    const float x0 = x[3 * i], x1 = x[3 * i + 1], x2 = x[3 * i + 2];
    float a0, a1;
    enc3(tb, x0, x1, x2, rp.r[lv & 15], a0, a1);

    uint32_t hi, lo;
    split2(a0, a1, hi, lo);
    // evict-first streaming stores: don't let the 512MB scratch evict the tables from L2
    __stcs(&g_feat[(size_t)lv * NMAX + i], hi);
    __stcs(&g_feat[(size_t)(32 + lv) * NMAX + i], lo);
}

// ================= kernel B: 5-layer MLP via HMMA =================
// Weight fragment smem layout: layer*16384 + tile*512 + lane*16 = uint4 {bh0, bh1, bl0, bl1}
#define BTPB 256
#define BWARP 8
#define W22_OFF 81920
#define BSMEM (81920 + 256)

__global__ void __launch_bounds__(BTPB, 2)
mlp_kernel(const float* __restrict__ w10, const float* __restrict__ w11,
           const float* __restrict__ w12, const float* __restrict__ w20,
           const float* __restrict__ w21, const float* __restrict__ w22,
           const float* __restrict__ alphap,
           float* __restrict__ out, int N) {
    extern __shared__ char sm[];
    const int tid = threadIdx.x;
    const int wid = tid >> 5;
    const int lane = tid & 31;
    const int gq = lane >> 2;   // quad row 0..7
    const int cq = lane & 3;    // quad col 0..3

    // ---- stage weight fragments (interleaved hi/lo per lane: one LDS.128 per tile) ----
    {
        const float* Ws[5] = { w10, w11, w12, w20, w21 };
#pragma unroll 1
        for (int g = wid; g < 320; g += BWARP) {
            int layer = g >> 6;
            int rem = g & 63;
            int tile = rem >> 1;          // kt*8 + nt
            int j = rem & 1;              // b-register index
            int kt = tile >> 3;
            int k0 = kt * 16 + cq * 2 + j * 8;
            int n = (tile & 7) * 8 + gq;
            const float* W = Ws[layer];
            float v0 = __ldg(W + k0 * 64 + n);
            float v1 = __ldg(W + (k0 + 1) * 64 + n);
            uint32_t hi, lo;
            split2(v0, v1, hi, lo);
            char* base = sm + layer * 16384 + tile * 512 + lane * 16 + j * 4;
            *reinterpret_cast<uint32_t*>(base) = hi;        // bh.j
            *reinterpret_cast<uint32_t*>(base + 8) = lo;    // bl.j
        }
        if (tid < 64) ((float*)(sm + W22_OFF))[tid] = w22[tid];
    }
    __syncthreads();

    const float alpha = __ldg(alphap);
    const float beta = 1.f - alpha;

#pragma unroll 1
    for (int mt = 0; mt < 2; mt++) {
        const int base_row = blockIdx.x * BTPB + wid * 32 + mt * 16;
        uint32_t ahi[16], alo[16];

#pragma unroll
        for (int layer = 0; layer < 5; layer++) {
            float d[8][4];
#pragma unroll
            for (int nt = 0; nt < 8; nt++)
#pragma unroll
                for (int q = 0; q < 4; q++) d[nt][q] = 0.f;

            const char* wl = sm + layer * 16384;

#pragma unroll
            for (int kt = 0; kt < 4; kt++) {
                uint32_t Ah[4], Al[4];
                if (layer == 0) {
                    size_t p0 = (size_t)(kt * 8 + cq) * NMAX + base_row + gq;
                    Ah[0] = __ldcs(&g_feat[p0]);
                    Ah[1] = __ldcs(&g_feat[p0 + 8]);
                    Ah[2] = __ldcs(&g_feat[p0 + 4ull * NMAX]);
                    Ah[3] = __ldcs(&g_feat[p0 + 4ull * NMAX + 8]);
                    Al[0] = __ldcs(&g_feat[p0 + 32ull * NMAX]);
                    Al[1] = __ldcs(&g_feat[p0 + 32ull * NMAX + 8]);
                    Al[2] = __ldcs(&g_feat[p0 + 36ull * NMAX]);
                    Al[3] = __ldcs(&g_feat[p0 + 36ull * NMAX + 8]);
                } else {
#pragma unroll
                    for (int q = 0; q < 4; q++) { Ah[q] = ahi[kt * 4 + q]; Al[q] = alo[kt * 4 + q]; }
                }
#pragma unroll
                for (int nt = 0; nt < 8; nt++) {
                    uint4 w = *reinterpret_cast<const uint4*>(wl + (kt * 8 + nt) * 512 + lane * 16);
                    mma16816(d[nt], Ah, w.x, w.y);
                    mma16816(d[nt], Ah, w.z, w.w);
                    mma16816(d[nt], Al, w.x, w.y);
                }
            }

            if (layer < 4) {
#pragma unroll
                for (int nt = 0; nt < 8; nt++) {
#pragma unroll
                    for (int q = 0; q < 4; q++) d[nt][q] = fmaxf(d[nt][q], 0.f);
                    if (layer == 2) {
                        size_t pw = (size_t)(nt * 4 + cq) * NMAX + base_row + gq;
                        uint32_t h0 = __ldcs(&g_feat[pw]);
                        uint32_t l0 = __ldcs(&g_feat[pw + 32ull * NMAX]);
                        uint32_t h8 = __ldcs(&g_feat[pw + 8]);
                        uint32_t l8 = __ldcs(&g_feat[pw + 32ull * NMAX + 8]);
                        d[nt][0] = d[nt][0] * alpha + beta * bf2sum(h0, l0, 0);
                        d[nt][1] = d[nt][1] * alpha + beta * bf2sum(h0, l0, 1);
                        d[nt][2] = d[nt][2] * alpha + beta * bf2sum(h8, l8, 0);
                        d[nt][3] = d[nt][3] * alpha + beta * bf2sum(h8, l8, 1);
                    }
                }
#pragma unroll
                for (int kt = 0; kt < 4; kt++) {
                    split2(d[2 * kt][0],     d[2 * kt][1],     ahi[kt * 4 + 0], alo[kt * 4 + 0]);
                    split2(d[2 * kt][2],     d[2 * kt][3],     ahi[kt * 4 + 1], alo[kt * 4 + 1]);
                    split2(d[2 * kt + 1][0], d[2 * kt + 1][1], ahi[kt * 4 + 2], alo[kt * 4 + 2]);
                    split2(d[2 * kt + 1][2], d[2 * kt + 1][3], ahi[kt * 4 + 3], alo[kt * 4 + 3]);
                }
            } else {
                float s0 = 0.f, s1 = 0.f;
#pragma unroll
                for (int nt = 0; nt < 8; nt++) {
                    float2 wv = *reinterpret_cast<const float2*>(sm + W22_OFF + nt * 32 + cq * 8);
                    s0 = fmaf(fmaxf(d[nt][0], 0.f), wv.x, s0);
                    s0 = fmaf(fmaxf(d[nt][1], 0.f), wv.y, s0);
                    s1 = fmaf(fmaxf(d[nt][2], 0.f), wv.x, s1);
                    s1 = fmaf(fmaxf(d[nt][3], 0.f), wv.y, s1);
                }
                s0 += __shfl_xor_sync(0xFFFFFFFF, s0, 1);
                s0 += __shfl_xor_sync(0xFFFFFFFF, s0, 2);
                s1 += __shfl_xor_sync(0xFFFFFFFF, s1, 1);
                s1 += __shfl_xor_sync(0xFFFFFFFF, s1, 2);
                if (cq == 0) {
                    int r0 = base_row + gq;
                    if (r0 < N) out[r0] = s0;
                    if (r0 + 8 < N) out[r0 + 8] = s1;
                }
            }
        }
    }
}

extern "C" void kernel_launch(void* const* d_in, const int* in_sizes, int n_in,
                              void* d_out, int out_size) {
    (void)in_sizes; (void)n_in;
    const float* x      = (const float*)d_in[0];
    const float* t      = (const float*)d_in[1];
    const float* tbl_s  = (const float*)d_in[2];
    const float* tbl_d  = (const float*)d_in[3];
    const float* w10    = (const float*)d_in[4];
    const float* w11    = (const float*)d_in[5];
    const float* w12    = (const float*)d_in[6];
    const float* w20    = (const float*)d_in[7];
    const float* w21    = (const float*)d_in[8];
    const float* w22    = (const float*)d_in[9];
    const float* alpha  = (const float*)d_in[10];
    float* out = (float*)d_out;

    int N = out_size;
    if (N <= 0) return;
    if (N > NMAX) N = NMAX;

    // RES[l] = floor(16 * b^l), identical double-precision expr as reference
    ResParams rp;
    double b = pow(2048.0 / 16.0, 1.0 / 15.0);
    for (int l = 0; l < NLEV; l++)
        rp.r[l] = (int)floor(16.0 * pow(b, (double)l));

    // fold scalar t into dynamic tables (4D -> 3D)
    dim3 gridP(2048, 16);
    fuse_dyn_kernel<<<gridP, 256>>>(t, tbl_d, rp);

    dim3 gridA((N + 255) / 256, 32);
    encode_kernel<<<gridA, 256>>>(x, tbl_s, N, rp);

    cudaFuncSetAttribute(mlp_kernel, cudaFuncAttributeMaxDynamicSharedMemorySize, BSMEM);
    int blocksB = (N + BTPB - 1) / BTPB;
    mlp_kernel<<<blocksB, BTPB, BSMEM>>>(w10, w11, w12, w20, w21, w22, alpha, out, N);
}

// round 11
// speedup vs baseline: 1.4446x; 1.2335x over previous
#include <cuda_runtime.h>
#include <cuda_bf16.h>
#include <math.h>
#include <stdint.h>

#define NLEV 16
#define TMASK ((1u << 19) - 1u)
#define PR1 2654435761u
#define PR2 805459861u
#define PR3 3674653429u
#define NMAX 2097152

// plane-major feature scratch: word c of point i at g_feat[c*NMAX + i]
// c in [0,32): bf16x2 hi words; c+32: lo words. 64 * 2M * 4B = 512 MB.
__device__ uint32_t g_feat[64ull * NMAX];
// combined per-level table: (static.xy, time-fused-dynamic.zw) = 16 levels x 512K float4 = 128 MB
__device__ float4 g_tbl_comb[(size_t)NLEV << 19];

struct ResParams { int r[NLEV]; };

// ---------------- helpers ----------------
__device__ __forceinline__ void mma16816(float d[4], const uint32_t a[4], uint32_t b0, uint32_t b1) {
    asm volatile("mma.sync.aligned.m16n8k16.row.col.f32.bf16.bf16.f32 "
        "{%0,%1,%2,%3}, {%4,%5,%6,%7}, {%8,%9}, {%0,%1,%2,%3};"
        : "+f"(d[0]), "+f"(d[1]), "+f"(d[2]), "+f"(d[3])
        : "r"(a[0]), "r"(a[1]), "r"(a[2]), "r"(a[3]), "r"(b0), "r"(b1));
}

__device__ __forceinline__ void split2(float v0, float v1, uint32_t& hi, uint32_t& lo) {
    __nv_bfloat162 h, l;
    h.x = __float2bfloat16_rn(v0);
    h.y = __float2bfloat16_rn(v1);
    l.x = __float2bfloat16_rn(v0 - __bfloat162float(h.x));
    l.y = __float2bfloat16_rn(v1 - __bfloat162float(h.y));
    hi = *reinterpret_cast<uint32_t*>(&h);
    lo = *reinterpret_cast<uint32_t*>(&l);
}

__device__ __forceinline__ float bf2sum(uint32_t hi, uint32_t lo, int idx) {
    const __nv_bfloat162* h = reinterpret_cast<const __nv_bfloat162*>(&hi);
    const __nv_bfloat162* l = reinterpret_cast<const __nv_bfloat162*>(&lo);
    return idx == 0 ? (__bfloat162float(h->x) + __bfloat162float(l->x))
                    : (__bfloat162float(h->y) + __bfloat162float(l->y));
}

// elementwise lerps: a + f*(b-a)
__device__ __forceinline__ float2 lerp2(float2 a, float2 b, float f) {
    float2 r;
    r.x = fmaf(f, b.x - a.x, a.x);
    r.y = fmaf(f, b.y - a.y, a.y);
    return r;
}
__device__ __forceinline__ float4 lerp4(float4 a, float4 b, float f) {
    float4 r;
    r.x = fmaf(f, b.x - a.x, a.x);
    r.y = fmaf(f, b.y - a.y, a.y);
    r.z = fmaf(f, b.z - a.z, a.z);
    r.w = fmaf(f, b.w - a.w, a.w);
    return r;
}

// ================= kernel P: build combined table =================
// C[l][j] = (T_s[l][j].xy, ((1-f3)*T_d[l][j^hw0] + f3*T_d[l][j^hw1]).xy)
// XOR-by-constant maps aligned 256-entry blocks to aligned blocks -> coalesced.
__global__ void __launch_bounds__(256)
build_comb_kernel(const float* __restrict__ tptr,
                  const float* __restrict__ tbl_s,
                  const float* __restrict__ tbl_d, ResParams rp) {
    const int l = blockIdx.y;
    const unsigned j = blockIdx.x * 256 + threadIdx.x;
    const float tv = __ldg(tptr);
    const float p3 = tv * (float)rp.r[l];
    const float g3 = floorf(p3);
    const float f3 = p3 - g3;
    const unsigned i3 = (unsigned)(int)g3;
    const unsigned hw0 = (i3 * PR3) & TMASK;
    const unsigned hw1 = ((i3 + 1u) * PR3) & TMASK;
    const float2* ts = (const float2*)tbl_s + ((size_t)l << 19);
    const float2* td = (const float2*)tbl_d + ((size_t)l << 19);
    float2 s = __ldg(ts + j);
    float2 a = __ldg(td + (j ^ hw0));
    float2 b = __ldg(td + (j ^ hw1));
    float2 d = lerp2(a, b, f3);
    g_tbl_comb[((size_t)l << 19) + j] = make_float4(s.x, s.y, d.x, d.y);
}

// ================= kernel A: level-parallel encode on the combined table =================
// grid = (ceil(N/256), 16): one float4 gather per corner serves static AND dynamic.
__global__ void __launch_bounds__(256)
encode_kernel(const float* __restrict__ x, int N, ResParams rp) {
    const int i = blockIdx.x * 256 + threadIdx.x;
    if (i >= N) return;
    const int l = blockIdx.y;
    const float4* tb = g_tbl_comb + ((size_t)l << 19);

    const float x0 = x[3 * i], x1 = x[3 * i + 1], x2 = x[3 * i + 2];
    const float fr = (float)rp.r[l];
    float p0 = x0 * fr, p1 = x1 * fr, p2 = x2 * fr;
    float g0 = floorf(p0), g1 = floorf(p1), g2 = floorf(p2);
    float f0 = p0 - g0, f1 = p1 - g1, f2 = p2 - g2;
    unsigned i0 = (unsigned)(int)g0, i1 = (unsigned)(int)g1, i2 = (unsigned)(int)g2;
    unsigned hy0 = i1 * PR1, hy1 = hy0 + PR1;
    unsigned hz0 = i2 * PR2, hz1 = hz0 + PR2;
    unsigned hyz[4] = { hy0 ^ hz0, hy0 ^ hz1, hy1 ^ hz0, hy1 ^ hz1 };
    unsigned i0b = i0 + 1u;

    float4 vlo[4], vhi[4];
#pragma unroll
    for (int j = 0; j < 4; j++) {
        vlo[j] = __ldg(tb + ((i0  ^ hyz[j]) & TMASK));
        vhi[j] = __ldg(tb + ((i0b ^ hyz[j]) & TMASK));
    }
    float4 u0 = lerp4(vlo[0], vhi[0], f0);
    float4 u1 = lerp4(vlo[1], vhi[1], f0);
    float4 u2 = lerp4(vlo[2], vhi[2], f0);
    float4 u3 = lerp4(vlo[3], vhi[3], f0);
    float4 s0 = lerp4(u0, u2, f1);
    float4 s1 = lerp4(u1, u3, f1);
    float4 r  = lerp4(s0, s1, f2);

    uint32_t hs, ls, hd, ld;
    split2(r.x, r.y, hs, ls);   // static level l  -> plane l / 32+l
    split2(r.z, r.w, hd, ld);   // dynamic level l -> plane 16+l / 48+l
    __stcs(&g_feat[(size_t)l * NMAX + i], hs);
    __stcs(&g_feat[(size_t)(32 + l) * NMAX + i], ls);
    __stcs(&g_feat[(size_t)(16 + l) * NMAX + i], hd);
    __stcs(&g_feat[(size_t)(48 + l) * NMAX + i], ld);
}

// ================= kernel B: 5-layer MLP via HMMA =================
// Weight fragment smem layout: layer*16384 + tile*512 + lane*16 = uint4 {bh0, bh1, bl0, bl1}
#define BTPB 256
#define BWARP 8
#define W22_OFF 81920
#define BSMEM (81920 + 256)

__global__ void __launch_bounds__(BTPB, 2)
mlp_kernel(const float* __restrict__ w10, const float* __restrict__ w11,
           const float* __restrict__ w12, const float* __restrict__ w20,
           const float* __restrict__ w21, const float* __restrict__ w22,
           const float* __restrict__ alphap,
           float* __restrict__ out, int N) {
    extern __shared__ char sm[];
    const int tid = threadIdx.x;
    const int wid = tid >> 5;
    const int lane = tid & 31;
    const int gq = lane >> 2;   // quad row 0..7
    const int cq = lane & 3;    // quad col 0..3

    // ---- stage weight fragments (interleaved hi/lo per lane: one LDS.128 per tile) ----
    {
        const float* Ws[5] = { w10, w11, w12, w20, w21 };
#pragma unroll 1
        for (int g = wid; g < 320; g += BWARP) {
            int layer = g >> 6;
            int rem = g & 63;
            int tile = rem >> 1;          // kt*8 + nt
            int j = rem & 1;              // b-register index
            int kt = tile >> 3;
            int k0 = kt * 16 + cq * 2 + j * 8;
            int n = (tile & 7) * 8 + gq;
            const float* W = Ws[layer];
            float v0 = __ldg(W + k0 * 64 + n);
            float v1 = __ldg(W + (k0 + 1) * 64 + n);
            uint32_t hi, lo;
            split2(v0, v1, hi, lo);
            char* base = sm + layer * 16384 + tile * 512 + lane * 16 + j * 4;
            *reinterpret_cast<uint32_t*>(base) = hi;        // bh.j
            *reinterpret_cast<uint32_t*>(base + 8) = lo;    // bl.j
        }
        if (tid < 64) ((float*)(sm + W22_OFF))[tid] = w22[tid];
    }
    __syncthreads();

    const float alpha = __ldg(alphap);
    const float beta = 1.f - alpha;

#pragma unroll 1
    for (int mt = 0; mt < 2; mt++) {
        const int base_row = blockIdx.x * BTPB + wid * 32 + mt * 16;
        uint32_t ahi[16], alo[16];

#pragma unroll
        for (int layer = 0; layer < 5; layer++) {
            float d[8][4];
#pragma unroll
            for (int nt = 0; nt < 8; nt++)
#pragma unroll
                for (int q = 0; q < 4; q++) d[nt][q] = 0.f;

            const char* wl = sm + layer * 16384;

#pragma unroll
            for (int kt = 0; kt < 4; kt++) {
                uint32_t Ah[4], Al[4];
                if (layer == 0) {
                    size_t p0 = (size_t)(kt * 8 + cq) * NMAX + base_row + gq;
                    Ah[0] = __ldcs(&g_feat[p0]);
                    Ah[1] = __ldcs(&g_feat[p0 + 8]);
                    Ah[2] = __ldcs(&g_feat[p0 + 4ull * NMAX]);
                    Ah[3] = __ldcs(&g_feat[p0 + 4ull * NMAX + 8]);
                    Al[0] = __ldcs(&g_feat[p0 + 32ull * NMAX]);
                    Al[1] = __ldcs(&g_feat[p0 + 32ull * NMAX + 8]);
                    Al[2] = __ldcs(&g_feat[p0 + 36ull * NMAX]);
                    Al[3] = __ldcs(&g_feat[p0 + 36ull * NMAX + 8]);
                } else {
#pragma unroll
                    for (int q = 0; q < 4; q++) { Ah[q] = ahi[kt * 4 + q]; Al[q] = alo[kt * 4 + q]; }
                }
#pragma unroll
                for (int nt = 0; nt < 8; nt++) {
                    uint4 w = *reinterpret_cast<const uint4*>(wl + (kt * 8 + nt) * 512 + lane * 16);
                    mma16816(d[nt], Ah, w.x, w.y);
                    mma16816(d[nt], Ah, w.z, w.w);
                    mma16816(d[nt], Al, w.x, w.y);
                }
            }

            if (layer < 4) {
#pragma unroll
                for (int nt = 0; nt < 8; nt++) {
#pragma unroll
                    for (int q = 0; q < 4; q++) d[nt][q] = fmaxf(d[nt][q], 0.f);
                    if (layer == 2) {
                        size_t pw = (size_t)(nt * 4 + cq) * NMAX + base_row + gq;
                        uint32_t h0 = __ldcs(&g_feat[pw]);
                        uint32_t l0 = __ldcs(&g_feat[pw + 32ull * NMAX]);
                        uint32_t h8 = __ldcs(&g_feat[pw + 8]);
                        uint32_t l8 = __ldcs(&g_feat[pw + 32ull * NMAX + 8]);
                        d[nt][0] = d[nt][0] * alpha + beta * bf2sum(h0, l0, 0);
                        d[nt][1] = d[nt][1] * alpha + beta * bf2sum(h0, l0, 1);
                        d[nt][2] = d[nt][2] * alpha + beta * bf2sum(h8, l8, 0);
                        d[nt][3] = d[nt][3] * alpha + beta * bf2sum(h8, l8, 1);
                    }
                }
#pragma unroll
                for (int kt = 0; kt < 4; kt++) {
                    split2(d[2 * kt][0],     d[2 * kt][1],     ahi[kt * 4 + 0], alo[kt * 4 + 0]);
                    split2(d[2 * kt][2],     d[2 * kt][3],     ahi[kt * 4 + 1], alo[kt * 4 + 1]);
                    split2(d[2 * kt + 1][0], d[2 * kt + 1][1], ahi[kt * 4 + 2], alo[kt * 4 + 2]);
                    split2(d[2 * kt + 1][2], d[2 * kt + 1][3], ahi[kt * 4 + 3], alo[kt * 4 + 3]);
                }
            } else {
                float s0 = 0.f, s1 = 0.f;
#pragma unroll
                for (int nt = 0; nt < 8; nt++) {
                    float2 wv = *reinterpret_cast<const float2*>(sm + W22_OFF + nt * 32 + cq * 8);
                    s0 = fmaf(fmaxf(d[nt][0], 0.f), wv.x, s0);
                    s0 = fmaf(fmaxf(d[nt][1], 0.f), wv.y, s0);
                    s1 = fmaf(fmaxf(d[nt][2], 0.f), wv.x, s1);
                    s1 = fmaf(fmaxf(d[nt][3], 0.f), wv.y, s1);
                }
                s0 += __shfl_xor_sync(0xFFFFFFFF, s0, 1);
                s0 += __shfl_xor_sync(0xFFFFFFFF, s0, 2);
                s1 += __shfl_xor_sync(0xFFFFFFFF, s1, 1);
                s1 += __shfl_xor_sync(0xFFFFFFFF, s1, 2);
                if (cq == 0) {
                    int r0 = base_row + gq;
                    if (r0 < N) out[r0] = s0;
                    if (r0 + 8 < N) out[r0 + 8] = s1;
                }
            }
        }
    }
}

extern "C" void kernel_launch(void* const* d_in, const int* in_sizes, int n_in,
                              void* d_out, int out_size) {
    (void)in_sizes; (void)n_in;
    const float* x      = (const float*)d_in[0];
    const float* t      = (const float*)d_in[1];
    const float* tbl_s  = (const float*)d_in[2];
    const float* tbl_d  = (const float*)d_in[3];
    const float* w10    = (const float*)d_in[4];
    const float* w11    = (const float*)d_in[5];
    const float* w12    = (const float*)d_in[6];
    const float* w20    = (const float*)d_in[7];
    const float* w21    = (const float*)d_in[8];
    const float* w22    = (const float*)d_in[9];
    const float* alpha  = (const float*)d_in[10];
    float* out = (float*)d_out;

    int N = out_size;
    if (N <= 0) return;
    if (N > NMAX) N = NMAX;

    // RES[l] = floor(16 * b^l), identical double-precision expr as reference
    ResParams rp;
    double b = pow(2048.0 / 16.0, 1.0 / 15.0);
    for (int l = 0; l < NLEV; l++)
        rp.r[l] = (int)floor(16.0 * pow(b, (double)l));

    // build combined (static | time-fused dynamic) float4 table
    dim3 gridP(2048, 16);
    build_comb_kernel<<<gridP, 256>>>(t, tbl_s, tbl_d, rp);

    dim3 gridA((N + 255) / 256, 16);
    encode_kernel<<<gridA, 256>>>(x, N, rp);

    cudaFuncSetAttribute(mlp_kernel, cudaFuncAttributeMaxDynamicSharedMemorySize, BSMEM);
    int blocksB = (N + BTPB - 1) / BTPB;
    mlp_kernel<<<blocksB, BTPB, BSMEM>>>(w10, w11, w12, w20, w21, w22, alpha, out, N);
}

// round 12
// speedup vs baseline: 1.4623x; 1.0122x over previous
#include <cuda_runtime.h>
#include <cuda_bf16.h>
#include <math.h>
#include <stdint.h>

#define NLEV 16
#define TMASK ((1u << 19) - 1u)
#define PR1 2654435761u
#define PR2 805459861u
#define PR3 3674653429u
#define NMAX 2097152

// interleaved feature scratch: plane c in [0,32), point i: g_feat2[c*NMAX+i] = {hi_word, lo_word}
// 32 * 2M * 8B = 512 MB.
__device__ uint2 g_feat2[32ull * NMAX];
// combined per-level table: (static.xy, time-fused-dynamic.zw) = 16 levels x 512K float4 = 128 MB
__device__ float4 g_tbl_comb[(size_t)NLEV << 19];
// packed coordinates (x0,x1,x2,unused): 32 MB
__device__ float4 g_x4[NMAX];

struct ResParams { int r[NLEV]; };

// ---------------- helpers ----------------
__device__ __forceinline__ void mma16816(float d[4], const uint32_t a[4], uint32_t b0, uint32_t b1) {
    asm volatile("mma.sync.aligned.m16n8k16.row.col.f32.bf16.bf16.f32 "
        "{%0,%1,%2,%3}, {%4,%5,%6,%7}, {%8,%9}, {%0,%1,%2,%3};"
        : "+f"(d[0]), "+f"(d[1]), "+f"(d[2]), "+f"(d[3])
        : "r"(a[0]), "r"(a[1]), "r"(a[2]), "r"(a[3]), "r"(b0), "r"(b1));
}

// fast hi/lo bf16x2 split: 1 cvt + shift/mask reconstruct + 2 fsub + 1 cvt
__device__ __forceinline__ void split2(float v0, float v1, uint32_t& hi, uint32_t& lo) {
    uint32_t h;
    asm("cvt.rn.bf16x2.f32 %0, %1, %2;" : "=r"(h) : "f"(v1), "f"(v0));
    float h0 = __uint_as_float(h << 16);
    float h1 = __uint_as_float(h & 0xFFFF0000u);
    float l0 = v0 - h0, l1 = v1 - h1;
    uint32_t l;
    asm("cvt.rn.bf16x2.f32 %0, %1, %2;" : "=r"(l) : "f"(l1), "f"(l0));
    hi = h; lo = l;
}

// reconstruct fp32 feature from interleaved hi/lo words (idx 0 = low half, 1 = high half)
__device__ __forceinline__ float bf2sum(uint32_t hi, uint32_t lo, int idx) {
    uint32_t hb = idx == 0 ? (hi << 16) : (hi & 0xFFFF0000u);
    uint32_t lb = idx == 0 ? (lo << 16) : (lo & 0xFFFF0000u);
    return __uint_as_float(hb) + __uint_as_float(lb);
}

// elementwise lerps: a + f*(b-a)
__device__ __forceinline__ float2 lerp2(float2 a, float2 b, float f) {
    float2 r;
    r.x = fmaf(f, b.x - a.x, a.x);
    r.y = fmaf(f, b.y - a.y, a.y);
    return r;
}
__device__ __forceinline__ float4 lerp4(float4 a, float4 b, float f) {
    float4 r;
    r.x = fmaf(f, b.x - a.x, a.x);
    r.y = fmaf(f, b.y - a.y, a.y);
    r.z = fmaf(f, b.z - a.z, a.z);
    r.w = fmaf(f, b.w - a.w, a.w);
    return r;
}

// ================= kernel X: pack coordinates into float4 =================
__global__ void __launch_bounds__(256)
pack_x_kernel(const float* __restrict__ x, int N) {
    const int i = blockIdx.x * 256 + threadIdx.x;
    if (i >= N) return;
    g_x4[i] = make_float4(x[3 * i], x[3 * i + 1], x[3 * i + 2], 0.f);
}

// ================= kernel P: build combined table =================
// C[l][j] = (T_s[l][j].xy, ((1-f3)*T_d[l][j^hw0] + f3*T_d[l][j^hw1]).xy)
__global__ void __launch_bounds__(256)
build_comb_kernel(const float* __restrict__ tptr,
                  const float* __restrict__ tbl_s,
                  const float* __restrict__ tbl_d, ResParams rp) {
    const int l = blockIdx.y;
    const unsigned j = blockIdx.x * 256 + threadIdx.x;
    const float tv = __ldg(tptr);
    const float p3 = tv * (float)rp.r[l];
    const float g3 = floorf(p3);
    const float f3 = p3 - g3;
    const unsigned i3 = (unsigned)(int)g3;
    const unsigned hw0 = (i3 * PR3) & TMASK;
    const unsigned hw1 = ((i3 + 1u) * PR3) & TMASK;
    const float2* ts = (const float2*)tbl_s + ((size_t)l << 19);
    const float2* td = (const float2*)tbl_d + ((size_t)l << 19);
    float2 s = __ldg(ts + j);
    float2 a = __ldg(td + (j ^ hw0));
    float2 b = __ldg(td + (j ^ hw1));
    float2 d = lerp2(a, b, f3);
    g_tbl_comb[((size_t)l << 19) + j] = make_float4(s.x, s.y, d.x, d.y);
}

// ================= kernel A: level-parallel encode on the combined table =================
// grid = (ceil(N/256), 16): one float4 gather per corner serves static AND dynamic.
__global__ void __launch_bounds__(256)
encode_kernel(int N, ResParams rp) {
    const int i = blockIdx.x * 256 + threadIdx.x;
    if (i >= N) return;
    const int l = blockIdx.y;
    const float4* tb = g_tbl_comb + ((size_t)l << 19);

    const float4 xi = __ldg(&g_x4[i]);
    const float fr = (float)rp.r[l];
    float p0 = xi.x * fr, p1 = xi.y * fr, p2 = xi.z * fr;
    float g0 = floorf(p0), g1 = floorf(p1), g2 = floorf(p2);
    float f0 = p0 - g0, f1 = p1 - g1, f2 = p2 - g2;
    unsigned i0 = (unsigned)(int)g0, i1 = (unsigned)(int)g1, i2 = (unsigned)(int)g2;
    unsigned hy0 = i1 * PR1, hy1 = hy0 + PR1;
    unsigned hz0 = i2 * PR2, hz1 = hz0 + PR2;
    unsigned hyz[4] = { hy0 ^ hz0, hy0 ^ hz1, hy1 ^ hz0, hy1 ^ hz1 };
    unsigned i0b = i0 + 1u;

    float4 vlo[4], vhi[4];
#pragma unroll
    for (int j = 0; j < 4; j++) {
        vlo[j] = __ldg(tb + ((i0  ^ hyz[j]) & TMASK));
        vhi[j] = __ldg(tb + ((i0b ^ hyz[j]) & TMASK));
    }
    float4 u0 = lerp4(vlo[0], vhi[0], f0);
    float4 u1 = lerp4(vlo[1], vhi[1], f0);
    float4 u2 = lerp4(vlo[2], vhi[2], f0);
    float4 u3 = lerp4(vlo[3], vhi[3], f0);
    float4 s0 = lerp4(u0, u2, f1);
    float4 s1 = lerp4(u1, u3, f1);
    float4 r  = lerp4(s0, s1, f2);

    uint32_t hs, ls, hd, ld;
    split2(r.x, r.y, hs, ls);   // static level l  -> plane l
    split2(r.z, r.w, hd, ld);   // dynamic level l -> plane 16+l
    // evict-first streaming stores: don't let the 512MB scratch evict the tables from L2
    __stcs(&g_feat2[(size_t)l * NMAX + i], make_uint2(hs, ls));
    __stcs(&g_feat2[(size_t)(16 + l) * NMAX + i], make_uint2(hd, ld));
}

// ================= kernel B: 5-layer MLP via HMMA =================
// Weight fragment smem layout: layer*16384 + tile*512 + lane*16 = uint4 {bh0, bh1, bl0, bl1}
#define BTPB 256
#define BWARP 8
#define W22_OFF 81920
#define BSMEM (81920 + 256)

__global__ void __launch_bounds__(BTPB, 2)
mlp_kernel(const float* __restrict__ w10, const float* __restrict__ w11,
           const float* __restrict__ w12, const float* __restrict__ w20,
           const float* __restrict__ w21, const float* __restrict__ w22,
           const float* __restrict__ alphap,
           float* __restrict__ out, int N) {
    extern __shared__ char sm[];
    const int tid = threadIdx.x;
    const int wid = tid >> 5;
    const int lane = tid & 31;
    const int gq = lane >> 2;   // quad row 0..7
    const int cq = lane & 3;    // quad col 0..3

    // ---- stage weight fragments (interleaved hi/lo per lane: one LDS.128 per tile) ----
    {
        const float* Ws[5] = { w10, w11, w12, w20, w21 };
#pragma unroll 1
        for (int g = wid; g < 320; g += BWARP) {
            int layer = g >> 6;
            int rem = g & 63;
            int tile = rem >> 1;          // kt*8 + nt
            int j = rem & 1;              // b-register index
            int kt = tile >> 3;
            int k0 = kt * 16 + cq * 2 + j * 8;
            int n = (tile & 7) * 8 + gq;
            const float* W = Ws[layer];
            float v0 = __ldg(W + k0 * 64 + n);
            float v1 = __ldg(W + (k0 + 1) * 64 + n);
            uint32_t hi, lo;
            split2(v0, v1, hi, lo);
            char* base = sm + layer * 16384 + tile * 512 + lane * 16 + j * 4;
            *reinterpret_cast<uint32_t*>(base) = hi;        // bh.j
            *reinterpret_cast<uint32_t*>(base + 8) = lo;    // bl.j
        }
        if (tid < 64) ((float*)(sm + W22_OFF))[tid] = w22[tid];
    }
    __syncthreads();

    const float alpha = __ldg(alphap);
    const float beta = 1.f - alpha;

#pragma unroll 1
    for (int mt = 0; mt < 2; mt++) {
        const int base_row = blockIdx.x * BTPB + wid * 32 + mt * 16;
        uint32_t ahi[16], alo[16];

#pragma unroll
        for (int layer = 0; layer < 5; layer++) {
            float d[8][4];
#pragma unroll
            for (int nt = 0; nt < 8; nt++)
#pragma unroll
                for (int q = 0; q < 4; q++) d[nt][q] = 0.f;

            const char* wl = sm + layer * 16384;

#pragma unroll
            for (int kt = 0; kt < 4; kt++) {
                uint32_t Ah[4], Al[4];
                if (layer == 0) {
                    size_t p0 = (size_t)(kt * 8 + cq) * NMAX + base_row + gq;
                    uint2 a0 = __ldcs(&g_feat2[p0]);
                    uint2 a1 = __ldcs(&g_feat2[p0 + 8]);
                    uint2 a2 = __ldcs(&g_feat2[p0 + 4ull * NMAX]);
                    uint2 a3 = __ldcs(&g_feat2[p0 + 4ull * NMAX + 8]);
                    Ah[0] = a0.x; Al[0] = a0.y;
                    Ah[1] = a1.x; Al[1] = a1.y;
                    Ah[2] = a2.x; Al[2] = a2.y;
                    Ah[3] = a3.x; Al[3] = a3.y;
                } else {
#pragma unroll
                    for (int q = 0; q < 4; q++) { Ah[q] = ahi[kt * 4 + q]; Al[q] = alo[kt * 4 + q]; }
                }
#pragma unroll
                for (int nt = 0; nt < 8; nt++) {
                    uint4 w = *reinterpret_cast<const uint4*>(wl + (kt * 8 + nt) * 512 + lane * 16);
                    mma16816(d[nt], Ah, w.x, w.y);
                    mma16816(d[nt], Ah, w.z, w.w);
                    mma16816(d[nt], Al, w.x, w.y);
                }
            }

            if (layer < 4) {
#pragma unroll
                for (int nt = 0; nt < 8; nt++) {
#pragma unroll
                    for (int q = 0; q < 4; q++) d[nt][q] = fmaxf(d[nt][q], 0.f);
                    if (layer == 2) {
                        size_t pw = (size_t)(nt * 4 + cq) * NMAX + base_row + gq;
                        uint2 fa = __ldcs(&g_feat2[pw]);
                        uint2 fb = __ldcs(&g_feat2[pw + 8]);
                        d[nt][0] = d[nt][0] * alpha + beta * bf2sum(fa.x, fa.y, 0);
                        d[nt][1] = d[nt][1] * alpha + beta * bf2sum(fa.x, fa.y, 1);
                        d[nt][2] = d[nt][2] * alpha + beta * bf2sum(fb.x, fb.y, 0);
                        d[nt][3] = d[nt][3] * alpha + beta * bf2sum(fb.x, fb.y, 1);
                    }
                }
#pragma unroll
                for (int kt = 0; kt < 4; kt++) {
                    split2(d[2 * kt][0],     d[2 * kt][1],     ahi[kt * 4 + 0], alo[kt * 4 + 0]);
                    split2(d[2 * kt][2],     d[2 * kt][3],     ahi[kt * 4 + 1], alo[kt * 4 + 1]);
                    split2(d[2 * kt + 1][0], d[2 * kt + 1][1], ahi[kt * 4 + 2], alo[kt * 4 + 2]);
                    split2(d[2 * kt + 1][2], d[2 * kt + 1][3], ahi[kt * 4 + 3], alo[kt * 4 + 3]);
                }
            } else {
                float s0 = 0.f, s1 = 0.f;
#pragma unroll
                for (int nt = 0; nt < 8; nt++) {
                    float2 wv = *reinterpret_cast<const float2*>(sm + W22_OFF + nt * 32 + cq * 8);
                    s0 = fmaf(fmaxf(d[nt][0], 0.f), wv.x, s0);
                    s0 = fmaf(fmaxf(d[nt][1], 0.f), wv.y, s0);
                    s1 = fmaf(fmaxf(d[nt][2], 0.f), wv.x, s1);
                    s1 = fmaf(fmaxf(d[nt][3], 0.f), wv.y, s1);
                }
                s0 += __shfl_xor_sync(0xFFFFFFFF, s0, 1);
                s0 += __shfl_xor_sync(0xFFFFFFFF, s0, 2);
                s1 += __shfl_xor_sync(0xFFFFFFFF, s1, 1);
                s1 += __shfl_xor_sync(0xFFFFFFFF, s1, 2);
                if (cq == 0) {
                    int r0 = base_row + gq;
                    if (r0 < N) out[r0] = s0;
                    if (r0 + 8 < N) out[r0 + 8] = s1;
                }
            }
        }
    }
}

extern "C" void kernel_launch(void* const* d_in, const int* in_sizes, int n_in,
                              void* d_out, int out_size) {
    (void)in_sizes; (void)n_in;
    const float* x      = (const float*)d_in[0];
    const float* t      = (const float*)d_in[1];
    const float* tbl_s  = (const float*)d_in[2];
    const float* tbl_d  = (const float*)d_in[3];
    const float* w10    = (const float*)d_in[4];
    const float* w11    = (const float*)d_in[5];
    const float* w12    = (const float*)d_in[6];
    const float* w20    = (const float*)d_in[7];
    const float* w21    = (const float*)d_in[8];
    const float* w22    = (const float*)d_in[9];
    const float* alpha  = (const float*)d_in[10];
    float* out = (float*)d_out;

    int N = out_size;
    if (N <= 0) return;
    if (N > NMAX) N = NMAX;

    // RES[l] = floor(16 * b^l), identical double-precision expr as reference
    ResParams rp;
    double b = pow(2048.0 / 16.0, 1.0 / 15.0);
    for (int l = 0; l < NLEV; l++)
        rp.r[l] = (int)floor(16.0 * pow(b, (double)l));

    int blocksN = (N + 255) / 256;

    pack_x_kernel<<<blocksN, 256>>>(x, N);

    dim3 gridP(2048, 16);
    build_comb_kernel<<<gridP, 256>>>(t, tbl_s, tbl_d, rp);

    dim3 gridA(blocksN, 16);
    encode_kernel<<<gridA, 256>>>(N, rp);

    cudaFuncSetAttribute(mlp_kernel, cudaFuncAttributeMaxDynamicSharedMemorySize, BSMEM);
    int blocksB = (N + BTPB - 1) / BTPB;
    mlp_kernel<<<blocksB, BTPB, BSMEM>>>(w10, w11, w12, w20, w21, w22, alpha, out, N);
}